// round 10
// baseline (speedup 1.0000x reference)
#include <cuda_runtime.h>

// LSTMBrain: 2-layer LSTM (hidden=3) over [B=4096, T=2048], dense head 3->1.
// Round 10: R9 skeleton (8 lanes/element: 0-2 L1 units, 4-6 L2 units, 3/7
// dup; 4 elements/warp; 1024 warps ~ 2/SMSP; gate-pair f32x2 z; 7 MUFU/step)
// with two chain cuts:
//  - exchange via 6 PARALLEL shfl.sync (lat ~26, one latency in chain) instead
//    of STS + syncwarp + LDS (~60+ cyc). R3 proved shfl correctness; its wall
//    was MUFU count, already fixed here.
//  - z matvec tree'd: two 4-deep ffma2 halves + fadd2 (chain 20 vs 32).

typedef unsigned long long u64;

#define FULLM 0xFFFFFFFFu
#define LOG2E 1.4426950408889634f

__device__ __forceinline__ float fast_rcp(float x) {
    float r; asm("rcp.approx.f32 %0, %1;" : "=f"(r) : "f"(x)); return r;
}
__device__ __forceinline__ float fast_ex2(float x) {
    float r; asm("ex2.approx.f32 %0, %1;" : "=f"(r) : "f"(x)); return r;
}
__device__ __forceinline__ u64 ffma2(u64 a, u64 b, u64 c) {
    u64 d; asm("fma.rn.f32x2 %0, %1, %2, %3;" : "=l"(d) : "l"(a), "l"(b), "l"(c));
    return d;
}
__device__ __forceinline__ u64 fmul2(u64 a, u64 b) {
    u64 d; asm("mul.rn.f32x2 %0, %1, %2;" : "=l"(d) : "l"(a), "l"(b)); return d;
}
__device__ __forceinline__ u64 fadd2(u64 a, u64 b) {
    u64 d; asm("add.rn.f32x2 %0, %1, %2;" : "=l"(d) : "l"(a), "l"(b)); return d;
}
__device__ __forceinline__ u64 pack2(float lo, float hi) {
    u64 d; asm("mov.b64 %0, {%1, %2};" : "=l"(d) : "f"(lo), "f"(hi)); return d;
}
__device__ __forceinline__ void unpack2(u64 v, float& lo, float& hi) {
    asm("mov.b64 {%0, %1}, %2;" : "=f"(lo), "=f"(hi) : "l"(v));
}

__global__ void __launch_bounds__(32, 1) lstm2_r10_kernel(
    const float* __restrict__ state,
    const float* __restrict__ W1, const float* __restrict__ U1, const float* __restrict__ b1,
    const float* __restrict__ W2, const float* __restrict__ U2, const float* __restrict__ b2,
    const float* __restrict__ Wd, const float* __restrict__ bd,
    float* __restrict__ out, int B, int T)
{
    const int lane  = threadIdx.x & 31;
    const int lane8 = lane & 7;
    const int gbase = lane & ~7;               // group's first lane
    const int sub   = lane8 & 3;
    const int u     = (sub < 3) ? sub : 2;     // owned hidden unit (3/7 dup 2)
    const bool isL2 = (lane8 & 4) != 0;

    int e = blockIdx.x * 4 + (lane >> 3);      // element of this group
    const bool act = (e < B);
    if (!act) e = B - 1;

    // ---- gate-pair packed coefficients, pre-scaled into the ex2 domain ----
    // pair P0 = gates (i, f), pair P1 = gates (g, o); column(gate) = gate*3+u
    u64 AP[2], BIP[2], BP[3][2], CP[3][2];
#pragma unroll
    for (int pr = 0; pr < 2; ++pr) {
        const int glo = (pr == 0) ? 0 : 2;     // i or g
        const int ghi = (pr == 0) ? 1 : 3;     // f or o
        const int clo = glo * 3 + u, chi = ghi * 3 + u;
        const float slo = (glo == 2) ? (-2.0f * LOG2E) : (-LOG2E);
        const float shi = -LOG2E;
        if (isL2) {
            AP[pr]  = 0;
            BIP[pr] = pack2(__ldg(b2 + clo) * slo, __ldg(b2 + chi) * shi);
#pragma unroll
            for (int k = 0; k < 3; ++k) {
                BP[k][pr] = pack2(__ldg(W2 + k * 12 + clo) * slo,
                                  __ldg(W2 + k * 12 + chi) * shi);  // * s1
                CP[k][pr] = pack2(__ldg(U2 + k * 12 + clo) * slo,
                                  __ldg(U2 + k * 12 + chi) * shi);  // * h2
            }
        } else {
            AP[pr]  = pack2(__ldg(W1 + clo) * slo, __ldg(W1 + chi) * shi);
            BIP[pr] = pack2(__ldg(b1 + clo) * slo, __ldg(b1 + chi) * shi);
#pragma unroll
            for (int k = 0; k < 3; ++k) {
                BP[k][pr] = pack2(__ldg(U1 + k * 12 + clo) * slo,
                                  __ldg(U1 + k * 12 + chi) * shi);  // * s1
                CP[k][pr] = 0;
            }
        }
    }

    const float* xrow = state + (size_t)e * (size_t)T;

    float cc   = 0.f;                     // own-unit scaled cell state
    float outv = 0.f;                     // own-unit hidden output
    u64 S0 = 0, S1 = 0, S2 = 0;           // duplicated s1(t-1) broadcasts
    u64 H0 = 0, H1 = 0, H2 = 0;           // duplicated h2(t-2) broadcasts

    // STEP: one timestep. z tree'd (two 4-deep halves); 7 MUFU.
#define STEP(xv)                                                            \
    do {                                                                    \
        const u64 xp = pack2((xv), (xv));                                   \
        u64 za1 = ffma2(BP[1][0], S1,                                       \
                    ffma2(BP[0][0], S0, ffma2(AP[0], xp, BIP[0])));         \
        u64 zb1 = ffma2(BP[1][1], S1,                                       \
                    ffma2(BP[0][1], S0, ffma2(AP[1], xp, BIP[1])));         \
        u64 za2 = ffma2(CP[2][0], H2,                                       \
                    ffma2(CP[1][0], H1,                                     \
                      ffma2(CP[0][0], H0, fmul2(BP[2][0], S2))));           \
        u64 zb2 = ffma2(CP[2][1], H2,                                       \
                    ffma2(CP[1][1], H1,                                     \
                      ffma2(CP[0][1], H0, fmul2(BP[2][1], S2))));           \
        const u64 za = fadd2(za1, za2);                                     \
        const u64 zb = fadd2(zb1, zb2);                                     \
        float zi, zf, zg, zo;                                               \
        unpack2(za, zi, zf); unpack2(zb, zg, zo);                           \
        const float ei = fast_ex2(zi);                                      \
        const float ef = fast_ex2(zf);                                      \
        const float eg = fast_ex2(zg);                                      \
        const float eo = fast_ex2(zo);                                      \
        const float di = 1.0f + ei, df = 1.0f + ef;                         \
        const float dg = 1.0f + eg, dq = 1.0f + eo;                         \
        const float m  = di * dg;                                           \
        const float Rm = fast_rcp(m * df);                                  \
        const float sf  = Rm * m;     /* 1/df */                            \
        const float r02 = Rm * df;    /* 1/(di*dg) */                       \
        const float p = fmaf(2.0f * LOG2E, eg, -2.0f * LOG2E);              \
        cc = fmaf(sf, cc, p * r02);                                         \
        const float ec = fast_ex2(cc);                                      \
        const float dc = 1.0f + ec;                                         \
        const float Rq = fast_rcp(dc * dq);                                 \
        outv = (1.0f - ec) * Rq;      /* tanh(c) * sigmoid(o) */            \
    } while (0)

    // exchange: 6 parallel shfls (sources: gbase+0..2 = s1, gbase+4..6 = h2),
    // then repack to (v,v) u64 for the f32x2 z.
#define XCHG()                                                              \
    do {                                                                    \
        const float s0 = __shfl_sync(FULLM, outv, gbase + 0);               \
        const float s1 = __shfl_sync(FULLM, outv, gbase + 1);               \
        const float s2 = __shfl_sync(FULLM, outv, gbase + 2);               \
        const float h0 = __shfl_sync(FULLM, outv, gbase + 4);               \
        const float h1 = __shfl_sync(FULLM, outv, gbase + 5);               \
        const float h2 = __shfl_sync(FULLM, outv, gbase + 6);               \
        S0 = pack2(s0, s0); S1 = pack2(s1, s1); S2 = pack2(s2, s2);         \
        H0 = pack2(h0, h0); H1 = pack2(h1, h1); H2 = pack2(h2, h2);         \
    } while (0)

#define BODY(xv) do { STEP(xv); XCHG(); } while (0)

    // ---- prologue: t = 0 (L2 lanes reset), then t = 1..3 from first chunk
    float4 a4 = __ldg(reinterpret_cast<const float4*>(xrow));
    float4 nA = a4;
    if (T >= 8) nA = __ldg(reinterpret_cast<const float4*>(xrow + 4));

    STEP(a4.x);
    if (isL2) { cc = 0.f; outv = 0.f; }
    XCHG();
    BODY(a4.y);
    BODY(a4.z);
    BODY(a4.w);

    int t = 4;
    for (; t + 7 < T; t += 4) {
        a4 = nA;
        nA = __ldg(reinterpret_cast<const float4*>(xrow + t + 4));
        BODY(a4.x);
        BODY(a4.y);
        BODY(a4.z);
        BODY(a4.w);
    }
    if (t + 3 < T) {                      // last full chunk (already prefetched)
        a4 = nA;
        BODY(a4.x);
        BODY(a4.y);
        BODY(a4.z);
        BODY(a4.w);
        t += 4;
    }
    for (; t < T; ++t) {                  // scalar tail (not taken for T=2048)
        BODY(__ldg(xrow + t));
    }

    // ---- epilogue: one more step so L2 lanes produce h2(T-1). x unused by
    // L2 (A = 0); L1 lanes' output is never consumed.
    STEP(0.0f);
    const float F0 = __shfl_sync(FULLM, outv, gbase + 4);
    const float F1 = __shfl_sync(FULLM, outv, gbase + 5);
    const float F2 = __shfl_sync(FULLM, outv, gbase + 6);

    if (lane8 == 0 && act) {
        float r = __ldg(bd);
        r = fmaf(F0, __ldg(Wd + 0), r);
        r = fmaf(F1, __ldg(Wd + 1), r);
        r = fmaf(F2, __ldg(Wd + 2), r);
        out[e] = r;
    }

#undef STEP
#undef XCHG
#undef BODY
}

extern "C" void kernel_launch(void* const* d_in, const int* in_sizes, int n_in,
                              void* d_out, int out_size)
{
    const float* state = (const float*)d_in[0];
    const float* W1 = (const float*)d_in[1];
    const float* U1 = (const float*)d_in[2];
    const float* b1 = (const float*)d_in[3];
    const float* W2 = (const float*)d_in[4];
    const float* U2 = (const float*)d_in[5];
    const float* b2 = (const float*)d_in[6];
    const float* Wd = (const float*)d_in[7];
    const float* bd = (const float*)d_in[8];
    float* out = (float*)d_out;

    const int B = out_size;            // output is [1, B]
    const int T = in_sizes[0] / B;     // state is [B, T]

    const int elems_per_warp = 4;      // 4 groups x 8 lanes = 32
    const int blocks = (B + elems_per_warp - 1) / elems_per_warp;   // 1024
    lstm2_r10_kernel<<<blocks, 32>>>(state, W1, U1, b1, W2, U2, b2,
                                     Wd, bd, out, B, T);
}